// round 12
// baseline (speedup 1.0000x reference)
#include <cuda_runtime.h>
#include <math.h>
#include <stdint.h>

#define C_DIM 6625
#define D_DIM 96
#define N_ROWS 8192
#define EPS_F 1e-7f
#define BLOCK_T 256
#define WARPS_PER_BLOCK (BLOCK_T / 32)
#define GRID_B 1184   // 148 SMs x 8 blocks -> every residency slot filled

// Scratch (static device allocation — no dynamic alloc allowed).
__device__ float g_row_loss[N_ROWS];
__device__ int   g_row_counter = 0;   // dynamic row dispenser
__device__ int   g_done_count  = 0;   // completion tickets

__device__ __forceinline__ float max4(float4 q) {
    return fmaxf(fmaxf(q.x, q.y), fmaxf(q.z, q.w));
}

__device__ __forceinline__ float neg_inf() {
    return __int_as_float(0xff800000);
}

__global__ void __launch_bounds__(BLOCK_T, 8)   // force <=32 regs -> 8 blocks/SM
center_loss_fused_kernel(const float* __restrict__ features,
                         const float* __restrict__ predicts,
                         const float* __restrict__ centers,
                         float* __restrict__ out) {
    const int tid  = threadIdx.x;
    const int lane = tid & 31;

    // ============ persistent warp: dynamically grab rows until done ==========
    for (;;) {
        int row;
        if (lane == 0) row = atomicAdd(&g_row_counter, 1);
        row = __shfl_sync(0xffffffffu, row, 0);
        if (row >= N_ROWS) break;

        const float* __restrict__ p = predicts + (size_t)row * C_DIM;

        float best = neg_inf();
        int   bidx = C_DIM;  // sentinel larger than any real index

        // Row base misalignment: (row*C_DIM)%4 == row%4 (C_DIM%4==1).
        const int pro = (4 - (row & 3)) & 3;   // scalar floats before 16B align
        if (lane < pro) {
            float v = __ldg(p + lane);
            if (v > best) { best = v; bidx = lane; }
        }

        const float4* __restrict__ p4 = (const float4*)(p + pro);
        const int nvec  = (C_DIM - pro) >> 2;   // 1655 or 1656
        const int ibody = (nvec >> 6) << 6;     // body covers 64-vec chunks

        int i = lane;
        while (i < ibody) {
            // two independent 16B loads, then a short reduce
            float4 q0 = __ldg(p4 + i);
            float4 q1 = __ldg(p4 + i + 32);
            float m = fmaxf(max4(q0), max4(q1));
            if (m > best) {   // rare (~few times per row per lane)
                best = m;
                int b0 = pro + (i << 2);
                int b1 = pro + ((i + 32) << 2);
                if      (q0.x == m) bidx = b0;
                else if (q0.y == m) bidx = b0 + 1;
                else if (q0.z == m) bidx = b0 + 2;
                else if (q0.w == m) bidx = b0 + 3;
                else if (q1.x == m) bidx = b1;
                else if (q1.y == m) bidx = b1 + 1;
                else if (q1.z == m) bidx = b1 + 2;
                else                bidx = b1 + 3;
            }
            i += 64;
        }

        // Remainder vecs (up to 2 per lane).
        while (i < nvec) {
            float4 q = __ldg(p4 + i);
            float m = max4(q);
            if (m > best) {
                best = m;
                int b = pro + (i << 2);
                if      (q.x == m) bidx = b;
                else if (q.y == m) bidx = b + 1;
                else if (q.z == m) bidx = b + 2;
                else               bidx = b + 3;
            }
            i += 32;
        }

        // Scalar tail (up to 3 elements).
        for (int c = pro + (nvec << 2) + lane; c < C_DIM; c += 32) {
            float v = __ldg(p + c);
            if (v > best) { best = v; bidx = c; }
        }

        // Warp argmax reduce: larger value wins; tie -> smaller index.
        #pragma unroll
        for (int off = 16; off > 0; off >>= 1) {
            float ov = __shfl_down_sync(0xffffffffu, best, off);
            int   oi = __shfl_down_sync(0xffffffffu, bidx, off);
            if (ov > best || (ov == best && oi < bidx)) { best = ov; bidx = oi; }
        }
        const int label = __shfl_sync(0xffffffffu, bidx, 0);

        // ---------------- squared distance ||f - c_label||^2 ----------------
        {
            const float* __restrict__ f   = features + (size_t)row * D_DIM;
            const float* __restrict__ cen = centers  + (size_t)label * D_DIM;
            float acc = 0.0f;
            #pragma unroll
            for (int j = 0; j < D_DIM / 32; j++) {
                int d = lane + j * 32;
                float diff = __ldg(f + d) - __ldg(cen + d);
                acc = fmaf(diff, diff, acc);
            }
            #pragma unroll
            for (int off = 16; off > 0; off >>= 1)
                acc += __shfl_down_sync(0xffffffffu, acc, off);
            if (lane == 0) {
                // label column clips at EPS; the other C-1 masked zeros each
                // clip to EPS and are summed by the reference.
                g_row_loss[row] = fmaxf(acc, EPS_F) + (float)(C_DIM - 1) * EPS_F;
            }
        }
    }

    // ================= fused final reduction (last block, fixed order) ========
    __shared__ bool s_is_last;
    __shared__ float s_red[BLOCK_T];

    __threadfence();
    __syncthreads();
    if (tid == 0) {
        int ticket = atomicAdd(&g_done_count, 1);
        s_is_last = (ticket == GRID_B - 1);
    }
    __syncthreads();

    if (s_is_last) {
        float acc = 0.0f;
        for (int i2 = tid; i2 < N_ROWS; i2 += BLOCK_T)
            acc += g_row_loss[i2];
        s_red[tid] = acc;
        __syncthreads();
        #pragma unroll
        for (int st = BLOCK_T / 2; st > 0; st >>= 1) {
            if (tid < st) s_red[tid] += s_red[tid + st];
            __syncthreads();
        }
        if (tid == 0) {
            out[0] = s_red[0] / (float)N_ROWS;
            g_done_count  = 0;   // reset for next graph replay
            g_row_counter = 0;
        }
    }
}

extern "C" void kernel_launch(void* const* d_in, const int* in_sizes, int n_in,
                              void* d_out, int out_size) {
    const float* features = (const float*)d_in[0];  // [32,256,96]
    const float* predicts = (const float*)d_in[1];  // [32,256,6625]
    const float* centers  = (const float*)d_in[2];  // [6625,96]
    float* out = (float*)d_out;

    center_loss_fused_kernel<<<GRID_B, BLOCK_T>>>(features, predicts, centers, out);
}

// round 13
// speedup vs baseline: 1.2598x; 1.2598x over previous
#include <cuda_runtime.h>
#include <math.h>
#include <stdint.h>

#define C_DIM 6625
#define D_DIM 96
#define N_ROWS 8192
#define EPS_F 1e-7f
#define BLOCK_T 256
#define WARPS_PER_BLOCK (BLOCK_T / 32)
#define GRID_B (N_ROWS / WARPS_PER_BLOCK)   // 1024 blocks, one warp per row (static)

// Scratch (static device allocation — no dynamic alloc allowed).
__device__ float g_row_loss[N_ROWS];
__device__ int   g_done_count = 0;

__device__ __forceinline__ float max4(float4 q) {
    return fmaxf(fmaxf(q.x, q.y), fmaxf(q.z, q.w));
}

__device__ __forceinline__ float neg_inf() {
    return __int_as_float(0xff800000);
}

__global__ void __launch_bounds__(BLOCK_T, 8)   // force <=32 regs -> 8 blocks/SM
center_loss_fused_kernel(const float* __restrict__ features,
                         const float* __restrict__ predicts,
                         const float* __restrict__ centers,
                         float* __restrict__ out) {
    const int tid  = threadIdx.x;
    const int lane = tid & 31;
    const int warp = tid >> 5;
    const int row  = blockIdx.x * WARPS_PER_BLOCK + warp;

    // ================= per-row argmax over C (warp-collective) =================
    const float* __restrict__ p = predicts + (size_t)row * C_DIM;

    float best = neg_inf();
    int   bidx = C_DIM;  // sentinel larger than any real index

    // Row base misalignment: (row*C_DIM)%4 == row%4 (C_DIM%4==1).
    const int pro = (4 - (row & 3)) & 3;   // scalar floats before 16B alignment
    if (lane < pro) {
        float v = __ldg(p + lane);
        if (v > best) { best = v; bidx = lane; }
    }

    const float4* __restrict__ p4 = (const float4*)(p + pro);
    const int nvec  = (C_DIM - pro) >> 2;      // 1655 or 1656
    const int ibody = (nvec / 96) * 96;        // body: chunks of 96 vecs (3x32)

    int i = lane;
    while (i < ibody) {
        // three independent 16B loads (imm offsets +512B/+1024B share one
        // address pair), then a branch-free fmax tree
        float4 q0 = __ldg(p4 + i);
        float4 q1 = __ldg(p4 + i + 32);
        float4 q2 = __ldg(p4 + i + 64);
        float m = fmaxf(fmaxf(max4(q0), max4(q1)), max4(q2));
        if (m > best) {   // rare (~few times per row per lane)
            best = m;
            int b0 = pro + (i << 2);
            if      (q0.x == m) bidx = b0;
            else if (q0.y == m) bidx = b0 + 1;
            else if (q0.z == m) bidx = b0 + 2;
            else if (q0.w == m) bidx = b0 + 3;
            else if (q1.x == m) bidx = b0 + 128;
            else if (q1.y == m) bidx = b0 + 129;
            else if (q1.z == m) bidx = b0 + 130;
            else if (q1.w == m) bidx = b0 + 131;
            else if (q2.x == m) bidx = b0 + 256;
            else if (q2.y == m) bidx = b0 + 257;
            else if (q2.z == m) bidx = b0 + 258;
            else                bidx = b0 + 259;
        }
        i += 96;
    }

    // Remainder vecs (up to 23-24 per warp-stride pass).
    while (i < nvec) {
        float4 q = __ldg(p4 + i);
        float m = max4(q);
        if (m > best) {
            best = m;
            int b = pro + (i << 2);
            if      (q.x == m) bidx = b;
            else if (q.y == m) bidx = b + 1;
            else if (q.z == m) bidx = b + 2;
            else               bidx = b + 3;
        }
        i += 32;
    }

    // Scalar tail (up to 3 elements).
    for (int c = pro + (nvec << 2) + lane; c < C_DIM; c += 32) {
        float v = __ldg(p + c);
        if (v > best) { best = v; bidx = c; }
    }

    // Warp argmax reduce: larger value wins; tie -> smaller index.
    #pragma unroll
    for (int off = 16; off > 0; off >>= 1) {
        float ov = __shfl_down_sync(0xffffffffu, best, off);
        int   oi = __shfl_down_sync(0xffffffffu, bidx, off);
        if (ov > best || (ov == best && oi < bidx)) { best = ov; bidx = oi; }
    }
    const int label = __shfl_sync(0xffffffffu, bidx, 0);

    // ================= squared distance ||f - c_label||^2 =================
    {
        const float* __restrict__ f   = features + (size_t)row * D_DIM;
        const float* __restrict__ cen = centers  + (size_t)label * D_DIM;
        float acc = 0.0f;
        #pragma unroll
        for (int j = 0; j < D_DIM / 32; j++) {
            int d = lane + j * 32;
            float diff = __ldg(f + d) - __ldg(cen + d);
            acc = fmaf(diff, diff, acc);
        }
        #pragma unroll
        for (int off = 16; off > 0; off >>= 1)
            acc += __shfl_down_sync(0xffffffffu, acc, off);
        if (lane == 0) {
            // label column clips at EPS; the other C-1 masked zeros each clip
            // to EPS and are summed by the reference -> add (C-1)*EPS per row.
            g_row_loss[row] = fmaxf(acc, EPS_F) + (float)(C_DIM - 1) * EPS_F;
        }
    }

    // ================= fused final reduction (last block, fixed order) ========
    __shared__ bool s_is_last;
    __shared__ float s_red[BLOCK_T];

    __threadfence();
    __syncthreads();
    if (tid == 0) {
        int ticket = atomicAdd(&g_done_count, 1);
        s_is_last = (ticket == GRID_B - 1);
    }
    __syncthreads();

    if (s_is_last) {
        float acc = 0.0f;
        for (int i2 = tid; i2 < N_ROWS; i2 += BLOCK_T)
            acc += g_row_loss[i2];
        s_red[tid] = acc;
        __syncthreads();
        #pragma unroll
        for (int st = BLOCK_T / 2; st > 0; st >>= 1) {
            if (tid < st) s_red[tid] += s_red[tid + st];
            __syncthreads();
        }
        if (tid == 0) {
            out[0] = s_red[0] / (float)N_ROWS;
            g_done_count = 0;  // reset for next graph replay
        }
    }
}

extern "C" void kernel_launch(void* const* d_in, const int* in_sizes, int n_in,
                              void* d_out, int out_size) {
    const float* features = (const float*)d_in[0];  // [32,256,96]
    const float* predicts = (const float*)d_in[1];  // [32,256,6625]
    const float* centers  = (const float*)d_in[2];  // [6625,96]
    float* out = (float*)d_out;

    center_loss_fused_kernel<<<GRID_B, BLOCK_T>>>(features, predicts, centers, out);
}